// round 3
// baseline (speedup 1.0000x reference)
#include <cuda_runtime.h>
#include <cuda_bf16.h>
#include <cstdint>

// ---------------- problem constants ----------------
#define N_MI   100000
#define N_DI   50000
#define N_E    500000
#define N_L    200000
#define F_MI_C 256
#define F_DI_C 128
#define H_C    128

// ---------------- device scratch ----------------
__device__ float g_hA_mi[(size_t)N_MI * 256];
__device__ float g_hB_mi[(size_t)N_MI * 256];
__device__ float g_hA_di[(size_t)N_DI * 256];
__device__ float g_hB_di[(size_t)N_DI * 256];
__device__ float g_t_mi[(size_t)N_MI * 256];    // transforms / means
__device__ float g_t_di[(size_t)N_DI * 256];
__device__ float g_agg_mi[(size_t)N_MI * 128];
__device__ float g_agg_di[(size_t)N_DI * 128];

__device__ int g_rowptr_di[N_DI + 1];
__device__ int g_rowptr_mi[N_MI + 1];
__device__ int g_col_di[N_E];
__device__ int g_col_mi[N_E];
__device__ int g_cnt_di[N_DI];
__device__ int g_cnt_mi[N_MI];

// ---------------- CSR build ----------------
__global__ void count_edges(const int* __restrict__ src, const int* __restrict__ dst, int e) {
    int i = blockIdx.x * blockDim.x + threadIdx.x;
    if (i < e) {
        atomicAdd(&g_cnt_mi[src[i]], 1);
        atomicAdd(&g_cnt_di[dst[i]], 1);
    }
}

__global__ void scan2() {
    const int* cnt = blockIdx.x ? g_cnt_mi : g_cnt_di;
    int* rowptr    = blockIdx.x ? g_rowptr_mi : g_rowptr_di;
    int n          = blockIdx.x ? N_MI : N_DI;

    __shared__ int warpsum[32];
    __shared__ int s_running;
    int tid = threadIdx.x, lane = tid & 31, wid = tid >> 5;
    if (tid == 0) s_running = 0;
    __syncthreads();

    for (int base = 0; base < n; base += 1024) {
        int i = base + tid;
        int v = (i < n) ? cnt[i] : 0;
        int x = v;
        #pragma unroll
        for (int off = 1; off < 32; off <<= 1) {
            int t = __shfl_up_sync(0xffffffffu, x, off);
            if (lane >= off) x += t;
        }
        if (lane == 31) warpsum[wid] = x;
        __syncthreads();
        if (wid == 0) {
            int w = warpsum[lane];
            #pragma unroll
            for (int off = 1; off < 32; off <<= 1) {
                int t = __shfl_up_sync(0xffffffffu, w, off);
                if (lane >= off) w += t;
            }
            warpsum[lane] = w;
        }
        __syncthreads();
        int incl = x + (wid ? warpsum[wid - 1] : 0);
        int run = s_running;
        if (i < n) rowptr[i] = run + incl - v;
        __syncthreads();
        if (tid == 1023) s_running = run + warpsum[31];
        __syncthreads();
    }
    if (threadIdx.x == 0) rowptr[n] = s_running;
}

__global__ void fill_edges(const int* __restrict__ src, const int* __restrict__ dst, int e) {
    int i = blockIdx.x * blockDim.x + threadIdx.x;
    if (i < e) {
        int s = src[i], d = dst[i];
        int pd = g_rowptr_di[d] + atomicAdd(&g_cnt_di[d], 1);
        g_col_di[pd] = s;
        int pm = g_rowptr_mi[s] + atomicAdd(&g_cnt_mi[s], 1);
        g_col_mi[pm] = d;
    }
}

// ---------------- mean aggregation (vectorized, warp per dst row) ----------------
__global__ void agg_mean128(const float* __restrict__ x, const int* __restrict__ rowptr,
                            const int* __restrict__ col, float* __restrict__ out, int n) {
    int warp = (blockIdx.x * blockDim.x + threadIdx.x) >> 5;
    int lane = threadIdx.x & 31;
    if (warp >= n) return;
    int s = rowptr[warp], e = rowptr[warp + 1];
    float4 acc = make_float4(0.f, 0.f, 0.f, 0.f);
    int i = s;
    for (; i + 1 < e; i += 2) {
        float4 a = __ldg((const float4*)(x + (size_t)col[i] * 128) + lane);
        float4 b = __ldg((const float4*)(x + (size_t)col[i + 1] * 128) + lane);
        acc.x += a.x + b.x; acc.y += a.y + b.y;
        acc.z += a.z + b.z; acc.w += a.w + b.w;
    }
    if (i < e) {
        float4 a = __ldg((const float4*)(x + (size_t)col[i] * 128) + lane);
        acc.x += a.x; acc.y += a.y; acc.z += a.z; acc.w += a.w;
    }
    float inv = 1.f / fmaxf((float)(e - s), 1.f);
    acc.x *= inv; acc.y *= inv; acc.z *= inv; acc.w *= inv;
    ((float4*)(out + (size_t)warp * 128))[lane] = acc;
}

__global__ void agg_mean64(const float* __restrict__ x, const int* __restrict__ rowptr,
                           const int* __restrict__ col, float* __restrict__ out, int n) {
    int warp = (blockIdx.x * blockDim.x + threadIdx.x) >> 5;
    int lane = threadIdx.x & 31;
    if (warp >= n) return;
    int s = rowptr[warp], e = rowptr[warp + 1];
    float2 acc = make_float2(0.f, 0.f);
    int i = s;
    for (; i + 1 < e; i += 2) {
        float2 a = __ldg((const float2*)(x + (size_t)col[i] * 64) + lane);
        float2 b = __ldg((const float2*)(x + (size_t)col[i + 1] * 64) + lane);
        acc.x += a.x + b.x; acc.y += a.y + b.y;
    }
    if (i < e) {
        float2 a = __ldg((const float2*)(x + (size_t)col[i] * 64) + lane);
        acc.x += a.x; acc.y += a.y;
    }
    float inv = 1.f / fmaxf((float)(e - s), 1.f);
    acc.x *= inv; acc.y *= inv;
    ((float2*)(out + (size_t)warp * 64))[lane] = acc;
}

// ---------------- bf16x3 split tensor-core GEMM ----------------
// C[M,N] = A0[M,K]@B0[N,K]^T (+ A1@B1^T) (+bias) (+addend), optional relu.
// Each fp32 operand split x = hi + lo (bf16 each); C accumulates
// hi*hi + hi*lo + lo*hi in fp32 tensor-core MMAs (error ~2^-18).
__device__ __forceinline__ unsigned pack_bf16x2(float lo, float hi) {
    unsigned r;
    asm("cvt.rn.bf16x2.f32 %0, %1, %2;" : "=r"(r) : "f"(hi), "f"(lo));
    return r;
}

__device__ __forceinline__ void mma_bf16(float* c, const unsigned* a, const unsigned* b) {
    asm volatile(
        "mma.sync.aligned.m16n8k16.row.col.f32.bf16.bf16.f32 "
        "{%0,%1,%2,%3}, {%4,%5,%6,%7}, {%8,%9}, {%0,%1,%2,%3};"
        : "+f"(c[0]), "+f"(c[1]), "+f"(c[2]), "+f"(c[3])
        : "r"(a[0]), "r"(a[1]), "r"(a[2]), "r"(a[3]), "r"(b[0]), "r"(b[1]));
}

// convert 2 consecutive floats -> packed hi word + lo word
__device__ __forceinline__ void split2(float x0, float x1, unsigned& hw, unsigned& lw) {
    hw = pack_bf16x2(x0, x1);
    float h0 = __uint_as_float(hw << 16);
    float h1 = __uint_as_float(hw & 0xffff0000u);
    lw = pack_bf16x2(x0 - h0, x1 - h1);
}

__global__ void __launch_bounds__(256, 2) bf16x3_gemm(
    const float* __restrict__ A0, const float* __restrict__ B0,
    const float* __restrict__ A1, const float* __restrict__ B1,
    const float* __restrict__ bias, const float* __restrict__ addend,
    float* __restrict__ C, int M, int N, int K, int relu) {

    constexpr int BM = 128, BN = 64, BK = 32;
    constexpr int KW = 20;  // 16 k-pair words + 4 pad (conflict-free fragment LDS)

    __shared__ unsigned As_hi[BM][KW], As_lo[BM][KW];
    __shared__ unsigned Bs_hi[BN][KW], Bs_lo[BN][KW];

    const int tid = threadIdx.x;
    const int lane = tid & 31, wid = tid >> 5;
    const int wm = wid & 1, wn = wid >> 1;         // 2 x 4 warps; warp tile 64x16
    const int group = lane >> 2, tig = lane & 3;
    const int m0 = blockIdx.y * BM, n0 = blockIdx.x * BN;

    float acc[4][2][4];
    #pragma unroll
    for (int i = 0; i < 4; ++i)
        #pragma unroll
        for (int j = 0; j < 2; ++j)
            #pragma unroll
            for (int q = 0; q < 4; ++q) acc[i][j][q] = 0.f;

    const int ktiles = K / BK;
    const int total = (A1 ? 2 : 1) * ktiles;

    float4 ra[4];
    float4 rb[2];

    auto load_tile = [&](int t) {
        const int p = (t >= ktiles) ? 1 : 0;
        const int kk0 = (t - p * ktiles) * BK;
        const float* Ap = p ? A1 : A0;
        const float* Bp = p ? B1 : B0;
        #pragma unroll
        for (int it = 0; it < 4; ++it) {
            int idx = it * 256 + tid, r = idx >> 3, c4 = (idx & 7) << 2;
            ra[it] = (m0 + r < M)
                ? *(const float4*)(Ap + (size_t)(m0 + r) * K + kk0 + c4)
                : make_float4(0.f, 0.f, 0.f, 0.f);
        }
        #pragma unroll
        for (int it = 0; it < 2; ++it) {
            int idx = it * 256 + tid, r = idx >> 3, c4 = (idx & 7) << 2;
            rb[it] = *(const float4*)(Bp + (size_t)(n0 + r) * K + kk0 + c4);
        }
    };

    load_tile(0);

    for (int t = 0; t < total; ++t) {
        __syncthreads();
        #pragma unroll
        for (int it = 0; it < 4; ++it) {
            int idx = it * 256 + tid, r = idx >> 3, w = (idx & 7) << 1;
            unsigned h0, l0, h1, l1;
            split2(ra[it].x, ra[it].y, h0, l0);
            split2(ra[it].z, ra[it].w, h1, l1);
            *(uint2*)&As_hi[r][w] = make_uint2(h0, h1);
            *(uint2*)&As_lo[r][w] = make_uint2(l0, l1);
        }
        #pragma unroll
        for (int it = 0; it < 2; ++it) {
            int idx = it * 256 + tid, r = idx >> 3, w = (idx & 7) << 1;
            unsigned h0, l0, h1, l1;
            split2(rb[it].x, rb[it].y, h0, l0);
            split2(rb[it].z, rb[it].w, h1, l1);
            *(uint2*)&Bs_hi[r][w] = make_uint2(h0, h1);
            *(uint2*)&Bs_lo[r][w] = make_uint2(l0, l1);
        }
        __syncthreads();
        if (t + 1 < total) load_tile(t + 1);   // keep LDGs in flight during MMA

        #pragma unroll
        for (int s = 0; s < 2; ++s) {          // two k16 slices per 32-k tile
            const int o = s * 8;
            unsigned ah[4][4], al[4][4];
            #pragma unroll
            for (int i = 0; i < 4; ++i) {
                int r = wm * 64 + i * 16 + group;
                ah[i][0] = As_hi[r][o + tig];     ah[i][1] = As_hi[r + 8][o + tig];
                ah[i][2] = As_hi[r][o + tig + 4]; ah[i][3] = As_hi[r + 8][o + tig + 4];
                al[i][0] = As_lo[r][o + tig];     al[i][1] = As_lo[r + 8][o + tig];
                al[i][2] = As_lo[r][o + tig + 4]; al[i][3] = As_lo[r + 8][o + tig + 4];
            }
            unsigned bh[2][2], bl[2][2];
            #pragma unroll
            for (int j = 0; j < 2; ++j) {
                int nl = wn * 16 + j * 8 + group;
                bh[j][0] = Bs_hi[nl][o + tig]; bh[j][1] = Bs_hi[nl][o + tig + 4];
                bl[j][0] = Bs_lo[nl][o + tig]; bl[j][1] = Bs_lo[nl][o + tig + 4];
            }
            #pragma unroll
            for (int i = 0; i < 4; ++i)
                #pragma unroll
                for (int j = 0; j < 2; ++j) {
                    mma_bf16(acc[i][j], al[i], bh[j]);
                    mma_bf16(acc[i][j], ah[i], bl[j]);
                    mma_bf16(acc[i][j], ah[i], bh[j]);
                }
        }
    }

    // epilogue
    #pragma unroll
    for (int i = 0; i < 4; ++i) {
        int row = m0 + wm * 64 + i * 16 + group;
        #pragma unroll
        for (int j = 0; j < 2; ++j) {
            int col = n0 + wn * 16 + j * 8 + 2 * tig;
            float b0 = 0.f, b1 = 0.f;
            if (bias) { b0 = __ldg(bias + col); b1 = __ldg(bias + col + 1); }
            if (row < M) {
                float v0 = acc[i][j][0] + b0, v1 = acc[i][j][1] + b1;
                if (addend) {
                    v0 += addend[(size_t)row * N + col];
                    v1 += addend[(size_t)row * N + col + 1];
                }
                if (relu) { v0 = fmaxf(v0, 0.f); v1 = fmaxf(v1, 0.f); }
                *(float2*)(C + (size_t)row * N + col) = make_float2(v0, v1);
            }
            int row2 = row + 8;
            if (row2 < M) {
                float v0 = acc[i][j][2] + b0, v1 = acc[i][j][3] + b1;
                if (addend) {
                    v0 += addend[(size_t)row2 * N + col];
                    v1 += addend[(size_t)row2 * N + col + 1];
                }
                if (relu) { v0 = fmaxf(v0, 0.f); v1 = fmaxf(v1, 0.f); }
                *(float2*)(C + (size_t)row2 * N + col) = make_float2(v0, v1);
            }
        }
    }
}

static void launch_gemm(const float* A0, const float* B0,
                        const float* A1, const float* B1,
                        const float* bias, const float* addend,
                        float* C, int M, int N, int K, int relu) {
    bf16x3_gemm<<<dim3(N / 64, (M + 127) / 128), 256>>>(
        A0, B0, A1, B1, bias, addend, C, M, N, K, relu);
}

// ---------------- classifier ----------------
__global__ void dot64(const float* __restrict__ hmi, const float* __restrict__ hdi,
                      const int* __restrict__ lsrc, const int* __restrict__ ldst,
                      float* __restrict__ out, int L) {
    int warp = (blockIdx.x * blockDim.x + threadIdx.x) >> 5;
    int lane = threadIdx.x & 31;
    if (warp >= L) return;
    const float2* a = (const float2*)(hmi + (size_t)lsrc[warp] * 64);
    const float2* b = (const float2*)(hdi + (size_t)ldst[warp] * 64);
    float2 av = a[lane], bv = b[lane];
    float p = av.x * bv.x + av.y * bv.y;
    #pragma unroll
    for (int off = 16; off; off >>= 1) p += __shfl_down_sync(0xffffffffu, p, off);
    if (lane == 0) out[warp] = p;
}

// ---------------- host orchestration ----------------
extern "C" void kernel_launch(void* const* d_in, const int* in_sizes, int n_in,
                              void* d_out, int out_size) {
    const float* x_mi   = (const float*)d_in[0];
    const float* x_di   = (const float*)d_in[1];
    const float* W_mi   = (const float*)d_in[2];
    const float* b_mi   = (const float*)d_in[3];
    const float* W_di   = (const float*)d_in[4];
    const float* b_di   = (const float*)d_in[5];
    const float* emb_mi = (const float*)d_in[6];
    const float* emb_di = (const float*)d_in[7];
    const float *Wl[3][2], *bl[3][2], *Wr[3][2];   // [layer][0=md,1=dm]
    for (int i = 0; i < 3; ++i)
        for (int r = 0; r < 2; ++r) {
            int base = 8 + i * 6 + r * 3;
            Wl[i][r] = (const float*)d_in[base];
            bl[i][r] = (const float*)d_in[base + 1];
            Wr[i][r] = (const float*)d_in[base + 2];
        }
    const int* edge_src  = (const int*)d_in[26];
    const int* edge_dst  = (const int*)d_in[27];
    const int* label_src = (const int*)d_in[28];
    const int* label_dst = (const int*)d_in[29];
    float* out = (float*)d_out;

    float *hA_mi, *hB_mi, *hA_di, *hB_di, *t_mi, *t_di, *agg_mi, *agg_di;
    int *rp_di, *rp_mi, *col_di, *col_mi, *cnt_di, *cnt_mi;
    cudaGetSymbolAddress((void**)&hA_mi, g_hA_mi);
    cudaGetSymbolAddress((void**)&hB_mi, g_hB_mi);
    cudaGetSymbolAddress((void**)&hA_di, g_hA_di);
    cudaGetSymbolAddress((void**)&hB_di, g_hB_di);
    cudaGetSymbolAddress((void**)&t_mi, g_t_mi);
    cudaGetSymbolAddress((void**)&t_di, g_t_di);
    cudaGetSymbolAddress((void**)&agg_mi, g_agg_mi);
    cudaGetSymbolAddress((void**)&agg_di, g_agg_di);
    cudaGetSymbolAddress((void**)&rp_di, g_rowptr_di);
    cudaGetSymbolAddress((void**)&rp_mi, g_rowptr_mi);
    cudaGetSymbolAddress((void**)&col_di, g_col_di);
    cudaGetSymbolAddress((void**)&col_mi, g_col_mi);
    cudaGetSymbolAddress((void**)&cnt_di, g_cnt_di);
    cudaGetSymbolAddress((void**)&cnt_mi, g_cnt_mi);

    const int EB = (N_E + 255) / 256;
    const int AG_DI = (N_DI + 7) / 8;   // 8 warps/block
    const int AG_MI = (N_MI + 7) / 8;

    // ---- CSR build ----
    cudaMemsetAsync(cnt_di, 0, N_DI * sizeof(int));
    cudaMemsetAsync(cnt_mi, 0, N_MI * sizeof(int));
    count_edges<<<EB, 256>>>(edge_src, edge_dst, N_E);
    scan2<<<2, 1024>>>();
    cudaMemsetAsync(cnt_di, 0, N_DI * sizeof(int));
    cudaMemsetAsync(cnt_mi, 0, N_MI * sizeof(int));
    fill_edges<<<EB, 256>>>(edge_src, edge_dst, N_E);

    // ---- input projections: h = x @ W^T + b + emb ----
    launch_gemm(x_mi, W_mi, nullptr, nullptr, b_mi, emb_mi, hA_mi, N_MI, H_C, F_MI_C, 0);
    launch_gemm(x_di, W_di, nullptr, nullptr, b_di, emb_di, hA_di, N_DI, H_C, F_DI_C, 0);

    // ---- Layer 1 (agg-first, 128 -> 256, relu) ----
    agg_mean128<<<AG_DI, 256>>>(hA_mi, rp_di, col_di, t_di, N_DI);
    agg_mean128<<<AG_MI, 256>>>(hA_di, rp_mi, col_mi, t_mi, N_MI);
    launch_gemm(t_di, Wl[0][0], hA_di, Wr[0][0], bl[0][0], nullptr, hB_di, N_DI, 256, 128, 1);
    launch_gemm(t_mi, Wl[0][1], hA_mi, Wr[0][1], bl[0][1], nullptr, hB_mi, N_MI, 256, 128, 1);

    // ---- Layer 2 (transform-first, 256 -> 128, relu) ----
    launch_gemm(hB_mi, Wl[1][0], nullptr, nullptr, nullptr, nullptr, t_mi, N_MI, 128, 256, 0);
    launch_gemm(hB_di, Wl[1][1], nullptr, nullptr, nullptr, nullptr, t_di, N_DI, 128, 256, 0);
    agg_mean128<<<AG_DI, 256>>>(t_mi, rp_di, col_di, agg_di, N_DI);
    agg_mean128<<<AG_MI, 256>>>(t_di, rp_mi, col_mi, agg_mi, N_MI);
    launch_gemm(hB_di, Wr[1][0], nullptr, nullptr, bl[1][0], agg_di, hA_di, N_DI, 128, 256, 1);
    launch_gemm(hB_mi, Wr[1][1], nullptr, nullptr, bl[1][1], agg_mi, hA_mi, N_MI, 128, 256, 1);

    // ---- Layer 3 (transform-first, 128 -> 64, no relu) ----
    launch_gemm(hA_mi, Wl[2][0], nullptr, nullptr, nullptr, nullptr, t_mi, N_MI, 64, 128, 0);
    launch_gemm(hA_di, Wl[2][1], nullptr, nullptr, nullptr, nullptr, t_di, N_DI, 64, 128, 0);
    agg_mean64<<<AG_DI, 256>>>(t_mi, rp_di, col_di, agg_di, N_DI);
    agg_mean64<<<AG_MI, 256>>>(t_di, rp_mi, col_mi, agg_mi, N_MI);
    launch_gemm(hA_di, Wr[2][0], nullptr, nullptr, bl[2][0], agg_di, hB_di, N_DI, 64, 128, 0);
    launch_gemm(hA_mi, Wr[2][1], nullptr, nullptr, bl[2][1], agg_mi, hB_mi, N_MI, 64, 128, 0);

    // ---- classifier ----
    dot64<<<(N_L + 7) / 8, 256>>>(hB_mi, hB_di, label_src, label_dst, out, N_L);
}

// round 5
// speedup vs baseline: 1.0804x; 1.0804x over previous
#include <cuda_runtime.h>
#include <cuda_bf16.h>
#include <cstdint>

// ---------------- problem constants ----------------
#define N_MI   100000
#define N_DI   50000
#define N_E    500000
#define N_L    200000
#define F_MI_C 256
#define F_DI_C 128
#define H_C    128

// ---------------- device scratch ----------------
__device__ float g_hA_mi[(size_t)N_MI * 256];
__device__ float g_hB_mi[(size_t)N_MI * 256];
__device__ float g_hA_di[(size_t)N_DI * 256];
__device__ float g_hB_di[(size_t)N_DI * 256];
__device__ float g_t_mi[(size_t)N_MI * 256];
__device__ float g_t_di[(size_t)N_DI * 256];

__device__ int g_rowptr_di[N_DI + 1];
__device__ int g_rowptr_mi[N_MI + 1];
__device__ int g_col_di[N_E];
__device__ int g_col_mi[N_E];
__device__ int g_cnt_di[N_DI];
__device__ int g_cnt_mi[N_MI];

// ---------------- helpers ----------------
__device__ __forceinline__ uint32_t smem_u32(const void* p) {
    uint32_t a;
    asm("{ .reg .u64 t; cvta.to.shared.u64 t, %1; cvt.u32.u64 %0, t; }"
        : "=r"(a) : "l"(p));
    return a;
}

__device__ __forceinline__ unsigned pack_bf16x2(float x0, float x1) {
    unsigned r;
    asm("cvt.rn.bf16x2.f32 %0, %1, %2;" : "=r"(r) : "f"(x1), "f"(x0));
    return r;
}
__device__ __forceinline__ void split2(float x0, float x1, unsigned& hw, unsigned& lw) {
    hw = pack_bf16x2(x0, x1);
    float h0 = __uint_as_float(hw << 16);
    float h1 = __uint_as_float(hw & 0xffff0000u);
    lw = pack_bf16x2(x0 - h0, x1 - h1);
}

__device__ __forceinline__ void mma_bf16(float* c, const unsigned* a, unsigned b0, unsigned b1) {
    asm volatile(
        "mma.sync.aligned.m16n8k16.row.col.f32.bf16.bf16.f32 "
        "{%0,%1,%2,%3}, {%4,%5,%6,%7}, {%8,%9}, {%0,%1,%2,%3};"
        : "+f"(c[0]), "+f"(c[1]), "+f"(c[2]), "+f"(c[3])
        : "r"(a[0]), "r"(a[1]), "r"(a[2]), "r"(a[3]), "r"(b0), "r"(b1));
}

__device__ __forceinline__ void ldsm_x4(uint32_t addr, unsigned& r0, unsigned& r1,
                                        unsigned& r2, unsigned& r3) {
    asm volatile("ldmatrix.sync.aligned.m8n8.x4.shared.b16 {%0,%1,%2,%3}, [%4];"
                 : "=r"(r0), "=r"(r1), "=r"(r2), "=r"(r3) : "r"(addr));
}

#define STS128(addr, a, b, c, d) \
    asm volatile("st.shared.v4.b32 [%0], {%1,%2,%3,%4};" \
                 :: "r"(addr), "r"(a), "r"(b), "r"(c), "r"(d))

// ---------------- bf16x3 mma.sync GEMM (ldmatrix + double buffer) ----------------
// C[M,N](row-major, ld=N) = A0[M,K]@B^T (+ A1@B1^T k-dual) (+bias)(+addend), opt relu.
// If A1: k-dual (B0 plane0, B1 plane1, bias full-width).
// Else if nsplit>0: column-split B (cols < nsplit use B0 no bias; cols >= nsplit use
//   B1 with bias indexed col-nsplit).
// Tile 128x64, K-chunk 64, 2-stage smem double buffer, SW-xor swizzled bf16 planes.
static constexpr int STAGE_BYTES = 49152;   // Ah 16K + Al 16K + Bh 8K + Bl 8K
static constexpr int GEMM_SMEM = 2 * STAGE_BYTES + 128;

__global__ void __launch_bounds__(256, 2) mma_gemm(
    const float* __restrict__ A0, const float* __restrict__ A1,
    const float* __restrict__ B0, const float* __restrict__ B1, int nsplit,
    const float* __restrict__ bias, const float* __restrict__ addend,
    float* __restrict__ C, int M, int N, int K, int relu) {

    extern __shared__ char smem_raw[];
    const uint32_t base = (smem_u32(smem_raw) + 127u) & ~127u;

    const int tid = threadIdx.x, lane = tid & 31, wid = tid >> 5;
    const int wm = wid & 1, wn = wid >> 1;           // 2 x 4 warps, warp tile 64x16
    const int group = lane >> 2, tig = lane & 3;
    const int m0 = blockIdx.y * 128, n0 = blockIdx.x * 64;

    // resolve B / bias per CTA
    const float *Bk0, *Bk1, *biasr = nullptr;
    if (A1) {
        Bk0 = B0 + (size_t)n0 * K;
        Bk1 = B1 + (size_t)n0 * K;
        if (bias) biasr = bias + n0;
    } else if (nsplit > 0) {
        if (n0 >= nsplit) {
            Bk0 = Bk1 = B1 + (size_t)(n0 - nsplit) * K;
            if (bias) biasr = bias + (n0 - nsplit);
        } else {
            Bk0 = Bk1 = B0 + (size_t)n0 * K;
        }
    } else {
        Bk0 = Bk1 = B0 + (size_t)n0 * K;
        if (bias) biasr = bias + n0;
    }

    float acc[4][2][4];
    #pragma unroll
    for (int i = 0; i < 4; ++i)
        #pragma unroll
        for (int j = 0; j < 2; ++j)
            #pragma unroll
            for (int q = 0; q < 4; ++q) acc[i][j][q] = 0.f;

    const int kch = K >> 6;                    // 64-wide k chunks per plane
    const int nch = A1 ? 2 * kch : kch;

    float4 ra[8];                               // A: 4 chunks x 2 float4
    float4 rb[4];                               // B: 2 chunks x 2 float4

    // thread -> (row, chunk) for stores/loads
    const int arow[4] = { (0*256+tid)>>3, (1*256+tid)>>3, (2*256+tid)>>3, (3*256+tid)>>3 };
    const int achk = tid & 7;
    const int brow[2] = { (0*256+tid)>>3, (1*256+tid)>>3 };

    auto prefetch = [&](int c) {
        const int p = (c >= kch) ? 1 : 0;
        const int k0 = (c - p * kch) << 6;
        const float* A = p ? A1 : A0;
        const float* B = p ? Bk1 : Bk0;
        #pragma unroll
        for (int it = 0; it < 4; ++it) {
            int gr = m0 + arow[it];
            const float* ap = A + (size_t)gr * K + k0 + achk * 8;
            if (gr < M) {
                ra[2*it]   = *(const float4*)ap;
                ra[2*it+1] = *(const float4*)(ap + 4);
            } else {
                ra[2*it] = ra[2*it+1] = make_float4(0.f, 0.f, 0.f, 0.f);
            }
        }
        #pragma unroll
        for (int it = 0; it < 2; ++it) {
            const float* bp = B + (size_t)brow[it] * K + k0 + achk * 8;
            rb[2*it]   = *(const float4*)bp;
            rb[2*it+1] = *(const float4*)(bp + 4);
        }
    };

    auto store_stage = [&](int st) {
        const uint32_t sah = base + st * STAGE_BYTES;
        const uint32_t sal = sah + 16384;
        const uint32_t sbh = sah + 32768;
        const uint32_t sbl = sah + 40960;
        #pragma unroll
        for (int it = 0; it < 4; ++it) {
            int r = arow[it];
            uint32_t off = (uint32_t)(r * 128 + ((achk ^ (r & 7)) << 4));
            unsigned h0,l0,h1,l1,h2,l2,h3,l3;
            split2(ra[2*it].x,   ra[2*it].y,   h0, l0);
            split2(ra[2*it].z,   ra[2*it].w,   h1, l1);
            split2(ra[2*it+1].x, ra[2*it+1].y, h2, l2);
            split2(ra[2*it+1].z, ra[2*it+1].w, h3, l3);
            STS128(sah + off, h0, h1, h2, h3);
            STS128(sal + off, l0, l1, l2, l3);
        }
        #pragma unroll
        for (int it = 0; it < 2; ++it) {
            int r = brow[it];
            uint32_t off = (uint32_t)(r * 128 + ((achk ^ (r & 7)) << 4));
            unsigned h0,l0,h1,l1,h2,l2,h3,l3;
            split2(rb[2*it].x,   rb[2*it].y,   h0, l0);
            split2(rb[2*it].z,   rb[2*it].w,   h1, l1);
            split2(rb[2*it+1].x, rb[2*it+1].y, h2, l2);
            split2(rb[2*it+1].z, rb[2*it+1].w, h3, l3);
            STS128(sbh + off, h0, h1, h2, h3);
            STS128(sbl + off, l0, l1, l2, l3);
        }
    };

    auto mma_stage = [&](int st) {
        const uint32_t sah = base + st * STAGE_BYTES;
        const uint32_t sal = sah + 16384;
        const uint32_t sbh = sah + 32768;
        const uint32_t sbl = sah + 40960;
        const int lrow = lane & 15, lsel = lane >> 4;
        #pragma unroll
        for (int s = 0; s < 4; ++s) {
            unsigned bh[4], bl[4];
            {
                int r = wn * 16 + lrow;
                int ch = 2 * s + lsel;
                uint32_t off = (uint32_t)(r * 128 + ((ch ^ (r & 7)) << 4));
                ldsm_x4(sbh + off, bh[0], bh[1], bh[2], bh[3]);
                ldsm_x4(sbl + off, bl[0], bl[1], bl[2], bl[3]);
            }
            #pragma unroll
            for (int i = 0; i < 4; ++i) {
                unsigned ah[4], al[4];
                int r = wm * 64 + i * 16 + lrow;
                int ch = 2 * s + lsel;
                uint32_t off = (uint32_t)(r * 128 + ((ch ^ (r & 7)) << 4));
                ldsm_x4(sah + off, ah[0], ah[1], ah[2], ah[3]);
                ldsm_x4(sal + off, al[0], al[1], al[2], al[3]);
                // j=0 uses {b[0], b[2]}, j=1 uses {b[1], b[3]}
                mma_bf16(acc[i][0], ah, bh[0], bh[2]);
                mma_bf16(acc[i][0], al, bh[0], bh[2]);
                mma_bf16(acc[i][0], ah, bl[0], bl[2]);
                mma_bf16(acc[i][1], ah, bh[1], bh[3]);
                mma_bf16(acc[i][1], al, bh[1], bh[3]);
                mma_bf16(acc[i][1], ah, bl[1], bl[3]);
            }
        }
    };

    prefetch(0);
    store_stage(0);
    __syncthreads();

    for (int c = 0; c < nch; ++c) {
        if (c + 1 < nch) prefetch(c + 1);
        mma_stage(c & 1);
        if (c + 1 < nch) store_stage((c + 1) & 1);
        __syncthreads();
    }

    // epilogue
    #pragma unroll
    for (int i = 0; i < 4; ++i) {
        int row = m0 + wm * 64 + i * 16 + group;
        #pragma unroll
        for (int j = 0; j < 2; ++j) {
            int nl = wn * 16 + j * 8 + 2 * tig;
            float b0 = 0.f, b1 = 0.f;
            if (biasr) { b0 = __ldg(biasr + nl); b1 = __ldg(biasr + nl + 1); }
            if (row < M) {
                float v0 = acc[i][j][0] + b0, v1 = acc[i][j][1] + b1;
                if (addend) {
                    const float* ap = addend + (size_t)row * N + n0 + nl;
                    v0 += ap[0]; v1 += ap[1];
                }
                if (relu) { v0 = fmaxf(v0, 0.f); v1 = fmaxf(v1, 0.f); }
                *(float2*)(C + (size_t)row * N + n0 + nl) = make_float2(v0, v1);
            }
            int row2 = row + 8;
            if (row2 < M) {
                float v0 = acc[i][j][2] + b0, v1 = acc[i][j][3] + b1;
                if (addend) {
                    const float* ap = addend + (size_t)row2 * N + n0 + nl;
                    v0 += ap[0]; v1 += ap[1];
                }
                if (relu) { v0 = fmaxf(v0, 0.f); v1 = fmaxf(v1, 0.f); }
                *(float2*)(C + (size_t)row2 * N + n0 + nl) = make_float2(v0, v1);
            }
        }
    }
}

// ---------------- CSR build ----------------
__global__ void count_edges(const int* __restrict__ src, const int* __restrict__ dst, int e) {
    int i = blockIdx.x * blockDim.x + threadIdx.x;
    if (i < e) {
        atomicAdd(&g_cnt_mi[src[i]], 1);
        atomicAdd(&g_cnt_di[dst[i]], 1);
    }
}

__global__ void scan2() {
    const int* cnt = blockIdx.x ? g_cnt_mi : g_cnt_di;
    int* rowptr    = blockIdx.x ? g_rowptr_mi : g_rowptr_di;
    int n          = blockIdx.x ? N_MI : N_DI;

    __shared__ int warpsum[32];
    __shared__ int s_running;
    int tid = threadIdx.x, lane = tid & 31, wid = tid >> 5;
    if (tid == 0) s_running = 0;
    __syncthreads();

    for (int base = 0; base < n; base += 1024) {
        int i = base + tid;
        int v = (i < n) ? cnt[i] : 0;
        int x = v;
        #pragma unroll
        for (int off = 1; off < 32; off <<= 1) {
            int t = __shfl_up_sync(0xffffffffu, x, off);
            if (lane >= off) x += t;
        }
        if (lane == 31) warpsum[wid] = x;
        __syncthreads();
        if (wid == 0) {
            int w = warpsum[lane];
            #pragma unroll
            for (int off = 1; off < 32; off <<= 1) {
                int t = __shfl_up_sync(0xffffffffu, w, off);
                if (lane >= off) w += t;
            }
            warpsum[lane] = w;
        }
        __syncthreads();
        int incl = x + (wid ? warpsum[wid - 1] : 0);
        int run = s_running;
        if (i < n) rowptr[i] = run + incl - v;
        __syncthreads();
        if (tid == 1023) s_running = run + warpsum[31];
        __syncthreads();
    }
    if (threadIdx.x == 0) rowptr[n] = s_running;
}

__global__ void fill_edges(const int* __restrict__ src, const int* __restrict__ dst, int e) {
    int i = blockIdx.x * blockDim.x + threadIdx.x;
    if (i < e) {
        int s = src[i], d = dst[i];
        int pd = g_rowptr_di[d] + atomicAdd(&g_cnt_di[d], 1);
        g_col_di[pd] = s;
        int pm = g_rowptr_mi[s] + atomicAdd(&g_cnt_mi[s], 1);
        g_col_mi[pm] = d;
    }
}

// ---------------- aggregation kernels ----------------
// L1: plain mean, src stride 128, width 128
__global__ void agg_plain128(const float* __restrict__ x, const int* __restrict__ rowptr,
                             const int* __restrict__ col, float* __restrict__ out, int n) {
    int warp = (blockIdx.x * blockDim.x + threadIdx.x) >> 5;
    int lane = threadIdx.x & 31;
    if (warp >= n) return;
    int s = rowptr[warp], e = rowptr[warp + 1];
    float4 acc = make_float4(0.f, 0.f, 0.f, 0.f);
    int i = s;
    for (; i + 1 < e; i += 2) {
        float4 a = __ldg((const float4*)(x + (size_t)col[i] * 128) + lane);
        float4 b = __ldg((const float4*)(x + (size_t)col[i + 1] * 128) + lane);
        acc.x += a.x + b.x; acc.y += a.y + b.y;
        acc.z += a.z + b.z; acc.w += a.w + b.w;
    }
    if (i < e) {
        float4 a = __ldg((const float4*)(x + (size_t)col[i] * 128) + lane);
        acc.x += a.x; acc.y += a.y; acc.z += a.z; acc.w += a.w;
    }
    float inv = 1.f / fmaxf((float)(e - s), 1.f);
    acc.x *= inv; acc.y *= inv; acc.z *= inv; acc.w *= inv;
    ((float4*)(out + (size_t)warp * 128))[lane] = acc;
}

// L2: out = relu(mean(srcC[:,0:128]) + rootC[:,128:256]); srcC/rootC stride 256
__global__ void agg_fused128(const float* __restrict__ srcC, const float* __restrict__ rootC,
                             const int* __restrict__ rowptr, const int* __restrict__ col,
                             float* __restrict__ out, int n) {
    int warp = (blockIdx.x * blockDim.x + threadIdx.x) >> 5;
    int lane = threadIdx.x & 31;
    if (warp >= n) return;
    int s = rowptr[warp], e = rowptr[warp + 1];
    float4 acc = make_float4(0.f, 0.f, 0.f, 0.f);
    int i = s;
    for (; i + 1 < e; i += 2) {
        float4 a = __ldg((const float4*)(srcC + (size_t)col[i] * 256) + lane);
        float4 b = __ldg((const float4*)(srcC + (size_t)col[i + 1] * 256) + lane);
        acc.x += a.x + b.x; acc.y += a.y + b.y;
        acc.z += a.z + b.z; acc.w += a.w + b.w;
    }
    if (i < e) {
        float4 a = __ldg((const float4*)(srcC + (size_t)col[i] * 256) + lane);
        acc.x += a.x; acc.y += a.y; acc.z += a.z; acc.w += a.w;
    }
    float inv = 1.f / fmaxf((float)(e - s), 1.f);
    float4 r = __ldg((const float4*)(rootC + (size_t)warp * 256 + 128) + lane);
    float4 v;
    v.x = fmaxf(acc.x * inv + r.x, 0.f);
    v.y = fmaxf(acc.y * inv + r.y, 0.f);
    v.z = fmaxf(acc.z * inv + r.z, 0.f);
    v.w = fmaxf(acc.w * inv + r.w, 0.f);
    ((float4*)(out + (size_t)warp * 128))[lane] = v;
}

// L3: out = mean(srcC[:,0:64]) + rootC[:,64:128]; stride 128, width 64, no relu
__global__ void agg_fused64(const float* __restrict__ srcC, const float* __restrict__ rootC,
                            const int* __restrict__ rowptr, const int* __restrict__ col,
                            float* __restrict__ out, int n) {
    int warp = (blockIdx.x * blockDim.x + threadIdx.x) >> 5;
    int lane = threadIdx.x & 31;
    if (warp >= n) return;
    int s = rowptr[warp], e = rowptr[warp + 1];
    float2 acc = make_float2(0.f, 0.f);
    int i = s;
    for (; i + 1 < e; i += 2) {
        float2 a = __ldg((const float2*)(srcC + (size_t)col[i] * 128) + lane);
        float2 b = __ldg((const float2*)(srcC + (size_t)col[i + 1] * 128) + lane);
        acc.x += a.x + b.x; acc.y += a.y + b.y;
    }
    if (i < e) {
        float2 a = __ldg((const float2*)(srcC + (size_t)col[i] * 128) + lane);
        acc.x += a.x; acc.y += a.y;
    }
    float inv = 1.f / fmaxf((float)(e - s), 1.f);
    float2 r = __ldg((const float2*)(rootC + (size_t)warp * 128 + 64) + lane);
    float2 v = make_float2(acc.x * inv + r.x, acc.y * inv + r.y);
    ((float2*)(out + (size_t)warp * 64))[lane] = v;
}

// ---------------- classifier ----------------
__global__ void dot64(const float* __restrict__ hmi, const float* __restrict__ hdi,
                      const int* __restrict__ lsrc, const int* __restrict__ ldst,
                      float* __restrict__ out, int L) {
    int warp = (blockIdx.x * blockDim.x + threadIdx.x) >> 5;
    int lane = threadIdx.x & 31;
    if (warp >= L) return;
    const float2* a = (const float2*)(hmi + (size_t)lsrc[warp] * 64);
    const float2* b = (const float2*)(hdi + (size_t)ldst[warp] * 64);
    float2 av = a[lane], bv = b[lane];
    float p = av.x * bv.x + av.y * bv.y;
    #pragma unroll
    for (int off = 16; off; off >>= 1) p += __shfl_down_sync(0xffffffffu, p, off);
    if (lane == 0) out[warp] = p;
}

// ---------------- host orchestration ----------------
static inline void launch_gemm(const float* A0, const float* A1,
                               const float* B0, const float* B1, int nsplit,
                               const float* bias, const float* addend,
                               float* C, int M, int N, int K, int relu) {
    mma_gemm<<<dim3(N / 64, (M + 127) / 128), 256, GEMM_SMEM>>>(
        A0, A1, B0, B1, nsplit, bias, addend, C, M, N, K, relu);
}

extern "C" void kernel_launch(void* const* d_in, const int* in_sizes, int n_in,
                              void* d_out, int out_size) {
    const float* x_mi   = (const float*)d_in[0];
    const float* x_di   = (const float*)d_in[1];
    const float* W_mi   = (const float*)d_in[2];
    const float* b_mi   = (const float*)d_in[3];
    const float* W_di   = (const float*)d_in[4];
    const float* b_di   = (const float*)d_in[5];
    const float* emb_mi = (const float*)d_in[6];
    const float* emb_di = (const float*)d_in[7];
    const float *Wl[3][2], *bl[3][2], *Wr[3][2];   // [layer][0=md,1=dm]
    for (int i = 0; i < 3; ++i)
        for (int r = 0; r < 2; ++r) {
            int base = 8 + i * 6 + r * 3;
            Wl[i][r] = (const float*)d_in[base];
            bl[i][r] = (const float*)d_in[base + 1];
            Wr[i][r] = (const float*)d_in[base + 2];
        }
    const int* edge_src  = (const int*)d_in[26];
    const int* edge_dst  = (const int*)d_in[27];
    const int* label_src = (const int*)d_in[28];
    const int* label_dst = (const int*)d_in[29];
    float* out = (float*)d_out;

    cudaFuncSetAttribute(mma_gemm, cudaFuncAttributeMaxDynamicSharedMemorySize, GEMM_SMEM);

    float *hA_mi, *hB_mi, *hA_di, *hB_di, *t_mi, *t_di;
    int *rp_di, *rp_mi, *col_di, *col_mi, *cnt_di, *cnt_mi;
    cudaGetSymbolAddress((void**)&hA_mi, g_hA_mi);
    cudaGetSymbolAddress((void**)&hB_mi, g_hB_mi);
    cudaGetSymbolAddress((void**)&hA_di, g_hA_di);
    cudaGetSymbolAddress((void**)&hB_di, g_hB_di);
    cudaGetSymbolAddress((void**)&t_mi, g_t_mi);
    cudaGetSymbolAddress((void**)&t_di, g_t_di);
    cudaGetSymbolAddress((void**)&rp_di, g_rowptr_di);
    cudaGetSymbolAddress((void**)&rp_mi, g_rowptr_mi);
    cudaGetSymbolAddress((void**)&col_di, g_col_di);
    cudaGetSymbolAddress((void**)&col_mi, g_col_mi);
    cudaGetSymbolAddress((void**)&cnt_di, g_cnt_di);
    cudaGetSymbolAddress((void**)&cnt_mi, g_cnt_mi);

    const int EB = (N_E + 255) / 256;
    const int AG_DI = (N_DI + 7) / 8;
    const int AG_MI = (N_MI + 7) / 8;

    // ---- CSR build ----
    cudaMemsetAsync(cnt_di, 0, N_DI * sizeof(int));
    cudaMemsetAsync(cnt_mi, 0, N_MI * sizeof(int));
    count_edges<<<EB, 256>>>(edge_src, edge_dst, N_E);
    scan2<<<2, 1024>>>();
    cudaMemsetAsync(cnt_di, 0, N_DI * sizeof(int));
    cudaMemsetAsync(cnt_mi, 0, N_MI * sizeof(int));
    fill_edges<<<EB, 256>>>(edge_src, edge_dst, N_E);

    // ---- input projections: h = x @ W^T + b + emb ----
    launch_gemm(x_mi, nullptr, W_mi, nullptr, 0, b_mi, emb_mi, hA_mi, N_MI, 128, F_MI_C, 0);
    launch_gemm(x_di, nullptr, W_di, nullptr, 0, b_di, emb_di, hA_di, N_DI, 128, F_DI_C, 0);

    // ---- Layer 1 (agg-first, 128 -> 256, relu), k-dual GEMM ----
    agg_plain128<<<AG_DI, 256>>>(hA_mi, rp_di, col_di, t_di, N_DI);
    agg_plain128<<<AG_MI, 256>>>(hA_di, rp_mi, col_mi, t_mi, N_MI);
    launch_gemm(t_di, hA_di, Wl[0][0], Wr[0][0], 0, bl[0][0], nullptr, hB_di, N_DI, 256, 128, 1);
    launch_gemm(t_mi, hA_mi, Wl[0][1], Wr[0][1], 0, bl[0][1], nullptr, hB_mi, N_MI, 256, 128, 1);

    // ---- Layer 2 (fused transform+root, 256 -> 128, relu) ----
    // C_mi = hB_mi @ [Wl2_md ; Wr2_dm]^T  (root half bias bl2_dm)
    launch_gemm(hB_mi, nullptr, Wl[1][0], Wr[1][1], 128, bl[1][1], nullptr, t_mi, N_MI, 256, 256, 0);
    // C_di = hB_di @ [Wl2_dm ; Wr2_md]^T  (root half bias bl2_md)
    launch_gemm(hB_di, nullptr, Wl[1][1], Wr[1][0], 128, bl[1][0], nullptr, t_di, N_DI, 256, 256, 0);
    agg_fused128<<<AG_DI, 256>>>(t_mi, t_di, rp_di, col_di, hA_di, N_DI);
    agg_fused128<<<AG_MI, 256>>>(t_di, t_mi, rp_mi, col_mi, hA_mi, N_MI);

    // ---- Layer 3 (fused transform+root, 128 -> 64, no relu) ----
    launch_gemm(hA_mi, nullptr, Wl[2][0], Wr[2][1], 64, bl[2][1], nullptr, t_mi, N_MI, 128, 128, 0);
    launch_gemm(hA_di, nullptr, Wl[2][1], Wr[2][0], 64, bl[2][0], nullptr, t_di, N_DI, 128, 128, 0);
    agg_fused64<<<AG_DI, 256>>>(t_mi, t_di, rp_di, col_di, hB_di, N_DI);
    agg_fused64<<<AG_MI, 256>>>(t_di, t_mi, rp_mi, col_mi, hB_mi, N_MI);

    // ---- classifier ----
    dot64<<<(N_L + 7) / 8, 256>>>(hB_mi, hB_di, label_src, label_dst, out, N_L);
}

// round 6
// speedup vs baseline: 1.1234x; 1.0398x over previous
#include <cuda_runtime.h>
#include <cuda_bf16.h>
#include <cstdint>

// ---------------- problem constants ----------------
#define N_MI   100000
#define N_DI   50000
#define N_E    500000
#define N_L    200000
#define F_MI_C 256
#define F_DI_C 128
#define H_C    128

// ---------------- device scratch ----------------
__device__ float g_hA_mi[(size_t)N_MI * 256];
__device__ float g_hB_mi[(size_t)N_MI * 256];
__device__ float g_hA_di[(size_t)N_DI * 256];
__device__ float g_hB_di[(size_t)N_DI * 256];
__device__ float g_t_mi[(size_t)N_MI * 256];
__device__ float g_t_di[(size_t)N_DI * 256];

__device__ int g_rowptr_di[N_DI + 1];
__device__ int g_rowptr_mi[N_MI + 1];
__device__ int g_col_di[N_E];
__device__ int g_col_mi[N_E];
__device__ int g_cnt_di[N_DI];
__device__ int g_cnt_mi[N_MI];

// ---------------- helpers ----------------
__device__ __forceinline__ uint32_t smem_u32(const void* p) {
    uint32_t a;
    asm("{ .reg .u64 t; cvta.to.shared.u64 t, %1; cvt.u32.u64 %0, t; }"
        : "=r"(a) : "l"(p));
    return a;
}

__device__ __forceinline__ unsigned pack_bf16x2(float x0, float x1) {
    unsigned r;
    asm("cvt.rn.bf16x2.f32 %0, %1, %2;" : "=r"(r) : "f"(x1), "f"(x0));
    return r;
}
__device__ __forceinline__ void split2(float x0, float x1, unsigned& hw, unsigned& lw) {
    hw = pack_bf16x2(x0, x1);
    float h0 = __uint_as_float(hw << 16);
    float h1 = __uint_as_float(hw & 0xffff0000u);
    lw = pack_bf16x2(x0 - h0, x1 - h1);
}

__device__ __forceinline__ void mma_bf16(float* c, const unsigned* a, unsigned b0, unsigned b1) {
    asm volatile(
        "mma.sync.aligned.m16n8k16.row.col.f32.bf16.bf16.f32 "
        "{%0,%1,%2,%3}, {%4,%5,%6,%7}, {%8,%9}, {%0,%1,%2,%3};"
        : "+f"(c[0]), "+f"(c[1]), "+f"(c[2]), "+f"(c[3])
        : "r"(a[0]), "r"(a[1]), "r"(a[2]), "r"(a[3]), "r"(b0), "r"(b1));
}

__device__ __forceinline__ void ldsm_x4(uint32_t addr, unsigned& r0, unsigned& r1,
                                        unsigned& r2, unsigned& r3) {
    asm volatile("ldmatrix.sync.aligned.m8n8.x4.shared.b16 {%0,%1,%2,%3}, [%4];"
                 : "=r"(r0), "=r"(r1), "=r"(r2), "=r"(r3) : "r"(addr));
}

#define STS128(addr, a, b, c, d) \
    asm volatile("st.shared.v4.b32 [%0], {%1,%2,%3,%4};" \
                 :: "r"(addr), "r"(a), "r"(b), "r"(c), "r"(d))

// ---------------- bf16x3 mma.sync GEMM, BM=64 x BN, K-chunk 64, double buffered ---
// C[M,N](ld=N) = A0@B^T (+A1@B1^T k-dual) (+bias)(+addend), opt relu.
// nsplit>0 (and !A1): cols < nsplit from B0 (no bias), cols >= nsplit from B1
// (bias indexed col-nsplit).
template <int BN>
__global__ void __launch_bounds__(256, 2) mma_gemm(
    const float* __restrict__ A0, const float* __restrict__ A1,
    const float* __restrict__ B0, const float* __restrict__ B1, int nsplit,
    const float* __restrict__ bias, const float* __restrict__ addend,
    float* __restrict__ C, int M, int N, int K, int relu) {

    constexpr int WN = BN / 4;         // warp n-extent (2m x 4n warp grid)
    constexpr int NT = WN / 8;         // n8 tiles per warp
    constexpr int NL = WN / 16;        // B ldsm.x4 per plane per k16
    constexpr int BSLOT = BN / 32;     // B 16B-chunk slots per thread
    constexpr uint32_t BPL = (uint32_t)BN * 128;        // B plane bytes
    constexpr uint32_t STAGE = 16384u + 2u * BPL;       // Ah8K+Al8K+Bh+Bl

    extern __shared__ char smem_raw[];
    const uint32_t base = (smem_u32(smem_raw) + 127u) & ~127u;

    const int tid = threadIdx.x, lane = tid & 31, wid = tid >> 5;
    const int wm = wid & 1, wn = wid >> 1;
    const int group = lane >> 2, tig = lane & 3;
    const int m0 = blockIdx.y * 64, n0 = blockIdx.x * BN;

    // resolve B / bias per CTA
    const float *Bk0, *Bk1, *biasr = nullptr;
    if (A1) {
        Bk0 = B0 + (size_t)n0 * K;
        Bk1 = B1 + (size_t)n0 * K;
        if (bias) biasr = bias + n0;
    } else if (nsplit > 0) {
        if (n0 >= nsplit) {
            Bk0 = Bk1 = B1 + (size_t)(n0 - nsplit) * K;
            if (bias) biasr = bias + (n0 - nsplit);
        } else {
            Bk0 = Bk1 = B0 + (size_t)n0 * K;
        }
    } else {
        Bk0 = Bk1 = B0 + (size_t)n0 * K;
        if (bias) biasr = bias + n0;
    }

    float acc[2][NT][4];
    #pragma unroll
    for (int i = 0; i < 2; ++i)
        #pragma unroll
        for (int j = 0; j < NT; ++j)
            #pragma unroll
            for (int q = 0; q < 4; ++q) acc[i][j][q] = 0.f;

    const int kch = K >> 6;
    const int nch = A1 ? 2 * kch : kch;

    float4 ra[4];                   // 2 slots x 8 floats
    float4 rb[2 * BSLOT];

    const int arow[2] = { tid >> 3, (256 + tid) >> 3 };
    const int ach = tid & 7;

    auto prefetch = [&](int c) {
        const int p = (c >= kch) ? 1 : 0;
        const int k0 = (c - p * kch) << 6;
        const float* A = p ? A1 : A0;
        const float* B = p ? Bk1 : Bk0;
        #pragma unroll
        for (int it = 0; it < 2; ++it) {
            int gr = m0 + arow[it];
            const float* ap = A + (size_t)gr * K + k0 + ach * 8;
            if (gr < M) {
                ra[2*it]   = *(const float4*)ap;
                ra[2*it+1] = *(const float4*)(ap + 4);
            } else {
                ra[2*it] = ra[2*it+1] = make_float4(0.f, 0.f, 0.f, 0.f);
            }
        }
        #pragma unroll
        for (int it = 0; it < BSLOT; ++it) {
            int r = (it * 256 + tid) >> 3;
            const float* bp = B + (size_t)r * K + k0 + ach * 8;
            rb[2*it]   = *(const float4*)bp;
            rb[2*it+1] = *(const float4*)(bp + 4);
        }
    };

    auto store_stage = [&](int st) {
        const uint32_t sah = base + (uint32_t)st * STAGE;
        const uint32_t sal = sah + 8192;
        const uint32_t sbh = sah + 16384;
        const uint32_t sbl = sbh + BPL;
        #pragma unroll
        for (int it = 0; it < 2; ++it) {
            int r = arow[it];
            uint32_t off = (uint32_t)(r * 128 + ((ach ^ (r & 7)) << 4));
            unsigned h0,l0,h1,l1,h2,l2,h3,l3;
            split2(ra[2*it].x,   ra[2*it].y,   h0, l0);
            split2(ra[2*it].z,   ra[2*it].w,   h1, l1);
            split2(ra[2*it+1].x, ra[2*it+1].y, h2, l2);
            split2(ra[2*it+1].z, ra[2*it+1].w, h3, l3);
            STS128(sah + off, h0, h1, h2, h3);
            STS128(sal + off, l0, l1, l2, l3);
        }
        #pragma unroll
        for (int it = 0; it < BSLOT; ++it) {
            int r = (it * 256 + tid) >> 3;
            uint32_t off = (uint32_t)(r * 128 + ((ach ^ (r & 7)) << 4));
            unsigned h0,l0,h1,l1,h2,l2,h3,l3;
            split2(rb[2*it].x,   rb[2*it].y,   h0, l0);
            split2(rb[2*it].z,   rb[2*it].w,   h1, l1);
            split2(rb[2*it+1].x, rb[2*it+1].y, h2, l2);
            split2(rb[2*it+1].z, rb[2*it+1].w, h3, l3);
            STS128(sbh + off, h0, h1, h2, h3);
            STS128(sbl + off, l0, l1, l2, l3);
        }
    };

    auto mma_stage = [&](int st) {
        const uint32_t sah = base + (uint32_t)st * STAGE;
        const uint32_t sal = sah + 8192;
        const uint32_t sbh = sah + 16384;
        const uint32_t sbl = sbh + BPL;
        const int lrow = lane & 15, lsel = lane >> 4;
        #pragma unroll
        for (int s = 0; s < 4; ++s) {
            const int ch = 2 * s + lsel;
            unsigned bh[NL][4], bl[NL][4];
            #pragma unroll
            for (int jl = 0; jl < NL; ++jl) {
                int r = wn * WN + jl * 16 + lrow;
                uint32_t off = (uint32_t)(r * 128 + ((ch ^ (r & 7)) << 4));
                ldsm_x4(sbh + off, bh[jl][0], bh[jl][1], bh[jl][2], bh[jl][3]);
                ldsm_x4(sbl + off, bl[jl][0], bl[jl][1], bl[jl][2], bl[jl][3]);
            }
            unsigned ah[2][4], al[2][4];
            #pragma unroll
            for (int i = 0; i < 2; ++i) {
                int r = wm * 32 + i * 16 + lrow;
                uint32_t off = (uint32_t)(r * 128 + ((ch ^ (r & 7)) << 4));
                ldsm_x4(sah + off, ah[i][0], ah[i][1], ah[i][2], ah[i][3]);
                ldsm_x4(sal + off, al[i][0], al[i][1], al[i][2], al[i][3]);
            }
            #pragma unroll
            for (int i = 0; i < 2; ++i)
                #pragma unroll
                for (int j = 0; j < NT; ++j) {
                    const int jl = j >> 1, sel = j & 1;
                    mma_bf16(acc[i][j], ah[i], bh[jl][sel], bh[jl][sel + 2]);
                    mma_bf16(acc[i][j], al[i], bh[jl][sel], bh[jl][sel + 2]);
                    mma_bf16(acc[i][j], ah[i], bl[jl][sel], bl[jl][sel + 2]);
                }
        }
    };

    prefetch(0);
    store_stage(0);
    __syncthreads();

    for (int c = 0; c < nch; ++c) {
        if (c + 1 < nch) prefetch(c + 1);
        mma_stage(c & 1);
        if (c + 1 < nch) store_stage((c + 1) & 1);
        __syncthreads();
    }

    // epilogue
    #pragma unroll
    for (int i = 0; i < 2; ++i) {
        int row = m0 + wm * 32 + i * 16 + group;
        #pragma unroll
        for (int j = 0; j < NT; ++j) {
            int nl = wn * WN + j * 8 + 2 * tig;
            float b0 = 0.f, b1 = 0.f;
            if (biasr) { b0 = __ldg(biasr + nl); b1 = __ldg(biasr + nl + 1); }
            if (row < M) {
                float v0 = acc[i][j][0] + b0, v1 = acc[i][j][1] + b1;
                if (addend) {
                    const float* ap = addend + (size_t)row * N + n0 + nl;
                    v0 += ap[0]; v1 += ap[1];
                }
                if (relu) { v0 = fmaxf(v0, 0.f); v1 = fmaxf(v1, 0.f); }
                *(float2*)(C + (size_t)row * N + n0 + nl) = make_float2(v0, v1);
            }
            int row2 = row + 8;
            if (row2 < M) {
                float v0 = acc[i][j][2] + b0, v1 = acc[i][j][3] + b1;
                if (addend) {
                    const float* ap = addend + (size_t)row2 * N + n0 + nl;
                    v0 += ap[0]; v1 += ap[1];
                }
                if (relu) { v0 = fmaxf(v0, 0.f); v1 = fmaxf(v1, 0.f); }
                *(float2*)(C + (size_t)row2 * N + n0 + nl) = make_float2(v0, v1);
            }
        }
    }
}

static constexpr int SMEM128 = 2 * (16384 + 2 * 128 * 128) + 128;  // 98432
static constexpr int SMEM64  = 2 * (16384 + 2 * 64 * 128) + 128;   // 65664

// ---------------- CSR build ----------------
__global__ void count_edges(const int* __restrict__ src, const int* __restrict__ dst, int e) {
    int i = blockIdx.x * blockDim.x + threadIdx.x;
    if (i < e) {
        atomicAdd(&g_cnt_mi[src[i]], 1);
        atomicAdd(&g_cnt_di[dst[i]], 1);
    }
}

__global__ void scan2() {
    const int* cnt = blockIdx.x ? g_cnt_mi : g_cnt_di;
    int* rowptr    = blockIdx.x ? g_rowptr_mi : g_rowptr_di;
    int n          = blockIdx.x ? N_MI : N_DI;

    __shared__ int warpsum[32];
    __shared__ int s_running;
    int tid = threadIdx.x, lane = tid & 31, wid = tid >> 5;
    if (tid == 0) s_running = 0;
    __syncthreads();

    for (int base = 0; base < n; base += 1024) {
        int i = base + tid;
        int v = (i < n) ? cnt[i] : 0;
        int x = v;
        #pragma unroll
        for (int off = 1; off < 32; off <<= 1) {
            int t = __shfl_up_sync(0xffffffffu, x, off);
            if (lane >= off) x += t;
        }
        if (lane == 31) warpsum[wid] = x;
        __syncthreads();
        if (wid == 0) {
            int w = warpsum[lane];
            #pragma unroll
            for (int off = 1; off < 32; off <<= 1) {
                int t = __shfl_up_sync(0xffffffffu, w, off);
                if (lane >= off) w += t;
            }
            warpsum[lane] = w;
        }
        __syncthreads();
        int incl = x + (wid ? warpsum[wid - 1] : 0);
        int run = s_running;
        if (i < n) rowptr[i] = run + incl - v;
        __syncthreads();
        if (tid == 1023) s_running = run + warpsum[31];
        __syncthreads();
    }
    if (threadIdx.x == 0) rowptr[n] = s_running;
}

__global__ void fill_edges(const int* __restrict__ src, const int* __restrict__ dst, int e) {
    int i = blockIdx.x * blockDim.x + threadIdx.x;
    if (i < e) {
        int s = src[i], d = dst[i];
        int pd = g_rowptr_di[d] + atomicAdd(&g_cnt_di[d], 1);
        g_col_di[pd] = s;
        int pm = g_rowptr_mi[s] + atomicAdd(&g_cnt_mi[s], 1);
        g_col_mi[pm] = d;
    }
}

// ---------------- aggregation kernels ----------------
__global__ void agg_plain128(const float* __restrict__ x, const int* __restrict__ rowptr,
                             const int* __restrict__ col, float* __restrict__ out, int n) {
    int warp = (blockIdx.x * blockDim.x + threadIdx.x) >> 5;
    int lane = threadIdx.x & 31;
    if (warp >= n) return;
    int s = rowptr[warp], e = rowptr[warp + 1];
    float4 acc = make_float4(0.f, 0.f, 0.f, 0.f);
    int i = s;
    for (; i + 1 < e; i += 2) {
        float4 a = __ldg((const float4*)(x + (size_t)col[i] * 128) + lane);
        float4 b = __ldg((const float4*)(x + (size_t)col[i + 1] * 128) + lane);
        acc.x += a.x + b.x; acc.y += a.y + b.y;
        acc.z += a.z + b.z; acc.w += a.w + b.w;
    }
    if (i < e) {
        float4 a = __ldg((const float4*)(x + (size_t)col[i] * 128) + lane);
        acc.x += a.x; acc.y += a.y; acc.z += a.z; acc.w += a.w;
    }
    float inv = 1.f / fmaxf((float)(e - s), 1.f);
    acc.x *= inv; acc.y *= inv; acc.z *= inv; acc.w *= inv;
    ((float4*)(out + (size_t)warp * 128))[lane] = acc;
}

// L2: out = relu(mean(srcC[:,0:128]) + rootC[:,128:256]); stride 256
__global__ void agg_fused128(const float* __restrict__ srcC, const float* __restrict__ rootC,
                             const int* __restrict__ rowptr, const int* __restrict__ col,
                             float* __restrict__ out, int n) {
    int warp = (blockIdx.x * blockDim.x + threadIdx.x) >> 5;
    int lane = threadIdx.x & 31;
    if (warp >= n) return;
    int s = rowptr[warp], e = rowptr[warp + 1];
    float4 acc = make_float4(0.f, 0.f, 0.f, 0.f);
    int i = s;
    for (; i + 1 < e; i += 2) {
        float4 a = __ldg((const float4*)(srcC + (size_t)col[i] * 256) + lane);
        float4 b = __ldg((const float4*)(srcC + (size_t)col[i + 1] * 256) + lane);
        acc.x += a.x + b.x; acc.y += a.y + b.y;
        acc.z += a.z + b.z; acc.w += a.w + b.w;
    }
    if (i < e) {
        float4 a = __ldg((const float4*)(srcC + (size_t)col[i] * 256) + lane);
        acc.x += a.x; acc.y += a.y; acc.z += a.z; acc.w += a.w;
    }
    float inv = 1.f / fmaxf((float)(e - s), 1.f);
    float4 r = __ldg((const float4*)(rootC + (size_t)warp * 256 + 128) + lane);
    float4 v;
    v.x = fmaxf(acc.x * inv + r.x, 0.f);
    v.y = fmaxf(acc.y * inv + r.y, 0.f);
    v.z = fmaxf(acc.z * inv + r.z, 0.f);
    v.w = fmaxf(acc.w * inv + r.w, 0.f);
    ((float4*)(out + (size_t)warp * 128))[lane] = v;
}

// L3: out = mean(srcC[:,0:64]) + rootC[:,64:128]; stride 128, width 64
__global__ void agg_fused64(const float* __restrict__ srcC, const float* __restrict__ rootC,
                            const int* __restrict__ rowptr, const int* __restrict__ col,
                            float* __restrict__ out, int n) {
    int warp = (blockIdx.x * blockDim.x + threadIdx.x) >> 5;
    int lane = threadIdx.x & 31;
    if (warp >= n) return;
    int s = rowptr[warp], e = rowptr[warp + 1];
    float2 acc = make_float2(0.f, 0.f);
    int i = s;
    for (; i + 1 < e; i += 2) {
        float2 a = __ldg((const float2*)(srcC + (size_t)col[i] * 128) + lane);
        float2 b = __ldg((const float2*)(srcC + (size_t)col[i + 1] * 128) + lane);
        acc.x += a.x + b.x; acc.y += a.y + b.y;
    }
    if (i < e) {
        float2 a = __ldg((const float2*)(srcC + (size_t)col[i] * 128) + lane);
        acc.x += a.x; acc.y += a.y;
    }
    float inv = 1.f / fmaxf((float)(e - s), 1.f);
    float2 r = __ldg((const float2*)(rootC + (size_t)warp * 128 + 64) + lane);
    float2 v = make_float2(acc.x * inv + r.x, acc.y * inv + r.y);
    ((float2*)(out + (size_t)warp * 64))[lane] = v;
}

// ---------------- classifier ----------------
__global__ void dot64(const float* __restrict__ hmi, const float* __restrict__ hdi,
                      const int* __restrict__ lsrc, const int* __restrict__ ldst,
                      float* __restrict__ out, int L) {
    int warp = (blockIdx.x * blockDim.x + threadIdx.x) >> 5;
    int lane = threadIdx.x & 31;
    if (warp >= L) return;
    const float2* a = (const float2*)(hmi + (size_t)lsrc[warp] * 64);
    const float2* b = (const float2*)(hdi + (size_t)ldst[warp] * 64);
    float2 av = a[lane], bv = b[lane];
    float p = av.x * bv.x + av.y * bv.y;
    #pragma unroll
    for (int off = 16; off; off >>= 1) p += __shfl_down_sync(0xffffffffu, p, off);
    if (lane == 0) out[warp] = p;
}

// ---------------- host orchestration ----------------
static inline void gemm128(const float* A0, const float* A1,
                           const float* B0, const float* B1, int nsplit,
                           const float* bias, const float* addend,
                           float* C, int M, int N, int K, int relu) {
    mma_gemm<128><<<dim3(N / 128, (M + 63) / 64), 256, SMEM128>>>(
        A0, A1, B0, B1, nsplit, bias, addend, C, M, N, K, relu);
}
static inline void gemm64(const float* A0, const float* A1,
                          const float* B0, const float* B1, int nsplit,
                          const float* bias, const float* addend,
                          float* C, int M, int N, int K, int relu) {
    mma_gemm<64><<<dim3(N / 64, (M + 63) / 64), 256, SMEM64>>>(
        A0, A1, B0, B1, nsplit, bias, addend, C, M, N, K, relu);
}

extern "C" void kernel_launch(void* const* d_in, const int* in_sizes, int n_in,
                              void* d_out, int out_size) {
    const float* x_mi   = (const float*)d_in[0];
    const float* x_di   = (const float*)d_in[1];
    const float* W_mi   = (const float*)d_in[2];
    const float* b_mi   = (const float*)d_in[3];
    const float* W_di   = (const float*)d_in[4];
    const float* b_di   = (const float*)d_in[5];
    const float* emb_mi = (const float*)d_in[6];
    const float* emb_di = (const float*)d_in[7];
    const float *Wl[3][2], *bl[3][2], *Wr[3][2];   // [layer][0=md,1=dm]
    for (int i = 0; i < 3; ++i)
        for (int r = 0; r < 2; ++r) {
            int base = 8 + i * 6 + r * 3;
            Wl[i][r] = (const float*)d_in[base];
            bl[i][r] = (const float*)d_in[base + 1];
            Wr[i][r] = (const float*)d_in[base + 2];
        }
    const int* edge_src  = (const int*)d_in[26];
    const int* edge_dst  = (const int*)d_in[27];
    const int* label_src = (const int*)d_in[28];
    const int* label_dst = (const int*)d_in[29];
    float* out = (float*)d_out;

    cudaFuncSetAttribute(mma_gemm<128>, cudaFuncAttributeMaxDynamicSharedMemorySize, SMEM128);
    cudaFuncSetAttribute(mma_gemm<64>,  cudaFuncAttributeMaxDynamicSharedMemorySize, SMEM64);

    float *hA_mi, *hB_mi, *hA_di, *hB_di, *t_mi, *t_di;
    int *rp_di, *rp_mi, *col_di, *col_mi, *cnt_di, *cnt_mi;
    cudaGetSymbolAddress((void**)&hA_mi, g_hA_mi);
    cudaGetSymbolAddress((void**)&hB_mi, g_hB_mi);
    cudaGetSymbolAddress((void**)&hA_di, g_hA_di);
    cudaGetSymbolAddress((void**)&hB_di, g_hB_di);
    cudaGetSymbolAddress((void**)&t_mi, g_t_mi);
    cudaGetSymbolAddress((void**)&t_di, g_t_di);
    cudaGetSymbolAddress((void**)&rp_di, g_rowptr_di);
    cudaGetSymbolAddress((void**)&rp_mi, g_rowptr_mi);
    cudaGetSymbolAddress((void**)&col_di, g_col_di);
    cudaGetSymbolAddress((void**)&col_mi, g_col_mi);
    cudaGetSymbolAddress((void**)&cnt_di, g_cnt_di);
    cudaGetSymbolAddress((void**)&cnt_mi, g_cnt_mi);

    const int EB = (N_E + 255) / 256;
    const int AG_DI = (N_DI + 7) / 8;
    const int AG_MI = (N_MI + 7) / 8;

    // ---- CSR build ----
    cudaMemsetAsync(cnt_di, 0, N_DI * sizeof(int));
    cudaMemsetAsync(cnt_mi, 0, N_MI * sizeof(int));
    count_edges<<<EB, 256>>>(edge_src, edge_dst, N_E);
    scan2<<<2, 1024>>>();
    cudaMemsetAsync(cnt_di, 0, N_DI * sizeof(int));
    cudaMemsetAsync(cnt_mi, 0, N_MI * sizeof(int));
    fill_edges<<<EB, 256>>>(edge_src, edge_dst, N_E);

    // ---- input projections: h = x @ W^T + b + emb ----
    gemm128(x_mi, nullptr, W_mi, nullptr, 0, b_mi, emb_mi, hA_mi, N_MI, 128, F_MI_C, 0);
    gemm128(x_di, nullptr, W_di, nullptr, 0, b_di, emb_di, hA_di, N_DI, 128, F_DI_C, 0);

    // ---- Layer 1 (agg-first, 128 -> 256, relu), k-dual ----
    agg_plain128<<<AG_DI, 256>>>(hA_mi, rp_di, col_di, t_di, N_DI);
    agg_plain128<<<AG_MI, 256>>>(hA_di, rp_mi, col_mi, t_mi, N_MI);
    gemm128(t_di, hA_di, Wl[0][0], Wr[0][0], 0, bl[0][0], nullptr, hB_di, N_DI, 256, 128, 1);
    gemm128(t_mi, hA_mi, Wl[0][1], Wr[0][1], 0, bl[0][1], nullptr, hB_mi, N_MI, 256, 128, 1);

    // ---- Layer 2 (fused transform+root, 256 -> 128, relu) ----
    gemm128(hB_mi, nullptr, Wl[1][0], Wr[1][1], 128, bl[1][1], nullptr, t_mi, N_MI, 256, 256, 0);
    gemm128(hB_di, nullptr, Wl[1][1], Wr[1][0], 128, bl[1][0], nullptr, t_di, N_DI, 256, 256, 0);
    agg_fused128<<<AG_DI, 256>>>(t_mi, t_di, rp_di, col_di, hA_di, N_DI);
    agg_fused128<<<AG_MI, 256>>>(t_di, t_mi, rp_mi, col_mi, hA_mi, N_MI);

    // ---- Layer 3 (fused transform+root, 128 -> 64, no relu) ----
    gemm64(hA_mi, nullptr, Wl[2][0], Wr[2][1], 64, bl[2][1], nullptr, t_mi, N_MI, 128, 128, 0);
    gemm64(hA_di, nullptr, Wl[2][1], Wr[2][0], 64, bl[2][0], nullptr, t_di, N_DI, 128, 128, 0);
    agg_fused64<<<AG_DI, 256>>>(t_mi, t_di, rp_di, col_di, hB_di, N_DI);
    agg_fused64<<<AG_MI, 256>>>(t_di, t_mi, rp_mi, col_mi, hB_mi, N_MI);

    // ---- classifier ----
    dot64<<<(N_L + 7) / 8, 256>>>(hB_mi, hB_di, label_src, label_dst, out, N_L);
}

// round 7
// speedup vs baseline: 1.1337x; 1.0092x over previous
#include <cuda_runtime.h>
#include <cuda_bf16.h>
#include <cstdint>

// ---------------- problem constants ----------------
#define N_MI   100000
#define N_DI   50000
#define N_E    500000
#define N_L    200000
#define F_MI_C 256
#define F_DI_C 128
#define H_C    128

// ---------------- device scratch ----------------
__device__ float g_hA_mi[(size_t)N_MI * 256];
__device__ float g_hB_mi[(size_t)N_MI * 256];
__device__ float g_hA_di[(size_t)N_DI * 256];
__device__ float g_hB_di[(size_t)N_DI * 256];
__device__ float g_t_mi[(size_t)N_MI * 256];
__device__ float g_t_di[(size_t)N_DI * 256];

__device__ int g_rowptr_di[N_DI + 1];
__device__ int g_rowptr_mi[N_MI + 1];
__device__ int g_col_di[N_E];
__device__ int g_col_mi[N_E];
__device__ int g_cnt_di[N_DI];
__device__ int g_cnt_mi[N_MI];

// ---------------- helpers ----------------
__device__ __forceinline__ uint32_t smem_u32(const void* p) {
    uint32_t a;
    asm("{ .reg .u64 t; cvta.to.shared.u64 t, %1; cvt.u32.u64 %0, t; }"
        : "=r"(a) : "l"(p));
    return a;
}

__device__ __forceinline__ unsigned pack_bf16x2(float x0, float x1) {
    unsigned r;
    asm("cvt.rn.bf16x2.f32 %0, %1, %2;" : "=r"(r) : "f"(x1), "f"(x0));
    return r;
}
__device__ __forceinline__ void split2(float x0, float x1, unsigned& hw, unsigned& lw) {
    hw = pack_bf16x2(x0, x1);
    float h0 = __uint_as_float(hw << 16);
    float h1 = __uint_as_float(hw & 0xffff0000u);
    lw = pack_bf16x2(x0 - h0, x1 - h1);
}

__device__ __forceinline__ void mma_bf16(float* c, const unsigned* a, unsigned b0, unsigned b1) {
    asm volatile(
        "mma.sync.aligned.m16n8k16.row.col.f32.bf16.bf16.f32 "
        "{%0,%1,%2,%3}, {%4,%5,%6,%7}, {%8,%9}, {%0,%1,%2,%3};"
        : "+f"(c[0]), "+f"(c[1]), "+f"(c[2]), "+f"(c[3])
        : "r"(a[0]), "r"(a[1]), "r"(a[2]), "r"(a[3]), "r"(b0), "r"(b1));
}

__device__ __forceinline__ void ldsm_x4(uint32_t addr, unsigned& r0, unsigned& r1,
                                        unsigned& r2, unsigned& r3) {
    asm volatile("ldmatrix.sync.aligned.m8n8.x4.shared.b16 {%0,%1,%2,%3}, [%4];"
                 : "=r"(r0), "=r"(r1), "=r"(r2), "=r"(r3) : "r"(addr));
}

#define STS128(addr, a, b, c, d) \
    asm volatile("st.shared.v4.b32 [%0], {%1,%2,%3,%4};" \
                 :: "r"(addr), "r"(a), "r"(b), "r"(c), "r"(d))

// ---------------- bf16x3 mma.sync GEMM, BM=64 x BN, K-chunk 64, double buffered ---
// C[M,N](ld=N) = A0@B^T (+A1@B1^T k-dual) (+bias)(+addend), opt relu.
// nsplit>0 (and !A1): cols < nsplit from B0 (no bias), cols >= nsplit from B1
// (bias indexed col-nsplit).
template <int BN>
__global__ void __launch_bounds__(256, 2) mma_gemm(
    const float* __restrict__ A0, const float* __restrict__ A1,
    const float* __restrict__ B0, const float* __restrict__ B1, int nsplit,
    const float* __restrict__ bias, const float* __restrict__ addend,
    float* __restrict__ C, int M, int N, int K, int relu) {

    constexpr int WN = BN / 4;         // warp n-extent (2m x 4n warp grid)
    constexpr int NT = WN / 8;         // n8 tiles per warp
    constexpr int NL = WN / 16;        // B ldsm.x4 per plane per k16
    constexpr int BSLOT = BN / 32;     // B 16B-chunk slots per thread
    constexpr uint32_t BPL = (uint32_t)BN * 128;        // B plane bytes
    constexpr uint32_t STAGE = 16384u + 2u * BPL;       // Ah8K+Al8K+Bh+Bl

    extern __shared__ char smem_raw[];
    const uint32_t base = (smem_u32(smem_raw) + 127u) & ~127u;

    const int tid = threadIdx.x, lane = tid & 31, wid = tid >> 5;
    const int wm = wid & 1, wn = wid >> 1;
    const int group = lane >> 2, tig = lane & 3;
    const int m0 = blockIdx.y * 64, n0 = blockIdx.x * BN;

    // resolve B / bias per CTA
    const float *Bk0, *Bk1, *biasr = nullptr;
    if (A1) {
        Bk0 = B0 + (size_t)n0 * K;
        Bk1 = B1 + (size_t)n0 * K;
        if (bias) biasr = bias + n0;
    } else if (nsplit > 0) {
        if (n0 >= nsplit) {
            Bk0 = Bk1 = B1 + (size_t)(n0 - nsplit) * K;
            if (bias) biasr = bias + (n0 - nsplit);
        } else {
            Bk0 = Bk1 = B0 + (size_t)n0 * K;
        }
    } else {
        Bk0 = Bk1 = B0 + (size_t)n0 * K;
        if (bias) biasr = bias + n0;
    }

    float acc[2][NT][4];
    #pragma unroll
    for (int i = 0; i < 2; ++i)
        #pragma unroll
        for (int j = 0; j < NT; ++j)
            #pragma unroll
            for (int q = 0; q < 4; ++q) acc[i][j][q] = 0.f;

    const int kch = K >> 6;
    const int nch = A1 ? 2 * kch : kch;

    float4 ra[4];                   // 2 slots x 8 floats
    float4 rb[2 * BSLOT];

    const int arow[2] = { tid >> 3, (256 + tid) >> 3 };
    const int ach = tid & 7;

    auto prefetch = [&](int c) {
        const int p = (c >= kch) ? 1 : 0;
        const int k0 = (c - p * kch) << 6;
        const float* A = p ? A1 : A0;
        const float* B = p ? Bk1 : Bk0;
        #pragma unroll
        for (int it = 0; it < 2; ++it) {
            int gr = m0 + arow[it];
            const float* ap = A + (size_t)gr * K + k0 + ach * 8;
            if (gr < M) {
                ra[2*it]   = *(const float4*)ap;
                ra[2*it+1] = *(const float4*)(ap + 4);
            } else {
                ra[2*it] = ra[2*it+1] = make_float4(0.f, 0.f, 0.f, 0.f);
            }
        }
        #pragma unroll
        for (int it = 0; it < BSLOT; ++it) {
            int r = (it * 256 + tid) >> 3;
            const float* bp = B + (size_t)r * K + k0 + ach * 8;
            rb[2*it]   = *(const float4*)bp;
            rb[2*it+1] = *(const float4*)(bp + 4);
        }
    };

    auto store_stage = [&](int st) {
        const uint32_t sah = base + (uint32_t)st * STAGE;
        const uint32_t sal = sah + 8192;
        const uint32_t sbh = sah + 16384;
        const uint32_t sbl = sbh + BPL;
        #pragma unroll
        for (int it = 0; it < 2; ++it) {
            int r = arow[it];
            uint32_t off = (uint32_t)(r * 128 + ((ach ^ (r & 7)) << 4));
            unsigned h0,l0,h1,l1,h2,l2,h3,l3;
            split2(ra[2*it].x,   ra[2*it].y,   h0, l0);
            split2(ra[2*it].z,   ra[2*it].w,   h1, l1);
            split2(ra[2*it+1].x, ra[2*it+1].y, h2, l2);
            split2(ra[2*it+1].z, ra[2*it+1].w, h3, l3);
            STS128(sah + off, h0, h1, h2, h3);
            STS128(sal + off, l0, l1, l2, l3);
        }
        #pragma unroll
        for (int it = 0; it < BSLOT; ++it) {
            int r = (it * 256 + tid) >> 3;
            uint32_t off = (uint32_t)(r * 128 + ((ach ^ (r & 7)) << 4));
            unsigned h0,l0,h1,l1,h2,l2,h3,l3;
            split2(rb[2*it].x,   rb[2*it].y,   h0, l0);
            split2(rb[2*it].z,   rb[2*it].w,   h1, l1);
            split2(rb[2*it+1].x, rb[2*it+1].y, h2, l2);
            split2(rb[2*it+1].z, rb[2*it+1].w, h3, l3);
            STS128(sbh + off, h0, h1, h2, h3);
            STS128(sbl + off, l0, l1, l2, l3);
        }
    };

    auto mma_stage = [&](int st) {
        const uint32_t sah = base + (uint32_t)st * STAGE;
        const uint32_t sal = sah + 8192;
        const uint32_t sbh = sah + 16384;
        const uint32_t sbl = sbh + BPL;
        const int lrow = lane & 15, lsel = lane >> 4;
        #pragma unroll
        for (int s = 0; s < 4; ++s) {
            const int ch = 2 * s + lsel;
            unsigned bh[NL][4], bl[NL][4];
            #pragma unroll
            for (int jl = 0; jl < NL; ++jl) {
                int r = wn * WN + jl * 16 + lrow;
                uint32_t off = (uint32_t)(r * 128 + ((ch ^ (r & 7)) << 4));
                ldsm_x4(sbh + off, bh[jl][0], bh[jl][1], bh[jl][2], bh[jl][3]);
                ldsm_x4(sbl + off, bl[jl][0], bl[jl][1], bl[jl][2], bl[jl][3]);
            }
            unsigned ah[2][4], al[2][4];
            #pragma unroll
            for (int i = 0; i < 2; ++i) {
                int r = wm * 32 + i * 16 + lrow;
                uint32_t off = (uint32_t)(r * 128 + ((ch ^ (r & 7)) << 4));
                ldsm_x4(sah + off, ah[i][0], ah[i][1], ah[i][2], ah[i][3]);
                ldsm_x4(sal + off, al[i][0], al[i][1], al[i][2], al[i][3]);
            }
            // pass-major: dependent MMAs on the same accumulator are separated
            // by 2*NT-1 independent MMAs (RAW latency hidden).
            #pragma unroll
            for (int pass = 0; pass < 3; ++pass) {
                #pragma unroll
                for (int i = 0; i < 2; ++i)
                    #pragma unroll
                    for (int j = 0; j < NT; ++j) {
                        const int jl = j >> 1, sel = j & 1;
                        const unsigned* af = (pass == 1) ? al[i] : ah[i];
                        const unsigned* bf = (pass == 2) ? bl[jl] : bh[jl];
                        mma_bf16(acc[i][j], af, bf[sel], bf[sel + 2]);
                    }
            }
        }
    };

    prefetch(0);
    store_stage(0);
    __syncthreads();

    for (int c = 0; c < nch; ++c) {
        if (c + 1 < nch) prefetch(c + 1);
        mma_stage(c & 1);
        if (c + 1 < nch) store_stage((c + 1) & 1);
        __syncthreads();
    }

    // epilogue
    #pragma unroll
    for (int i = 0; i < 2; ++i) {
        int row = m0 + wm * 32 + i * 16 + group;
        #pragma unroll
        for (int j = 0; j < NT; ++j) {
            int nl = wn * WN + j * 8 + 2 * tig;
            float b0 = 0.f, b1 = 0.f;
            if (biasr) { b0 = __ldg(biasr + nl); b1 = __ldg(biasr + nl + 1); }
            if (row < M) {
                float v0 = acc[i][j][0] + b0, v1 = acc[i][j][1] + b1;
                if (addend) {
                    const float* ap = addend + (size_t)row * N + n0 + nl;
                    v0 += ap[0]; v1 += ap[1];
                }
                if (relu) { v0 = fmaxf(v0, 0.f); v1 = fmaxf(v1, 0.f); }
                *(float2*)(C + (size_t)row * N + n0 + nl) = make_float2(v0, v1);
            }
            int row2 = row + 8;
            if (row2 < M) {
                float v0 = acc[i][j][2] + b0, v1 = acc[i][j][3] + b1;
                if (addend) {
                    const float* ap = addend + (size_t)row2 * N + n0 + nl;
                    v0 += ap[0]; v1 += ap[1];
                }
                if (relu) { v0 = fmaxf(v0, 0.f); v1 = fmaxf(v1, 0.f); }
                *(float2*)(C + (size_t)row2 * N + n0 + nl) = make_float2(v0, v1);
            }
        }
    }
}

static constexpr int SMEM128 = 2 * (16384 + 2 * 128 * 128) + 128;  // 98432
static constexpr int SMEM64  = 2 * (16384 + 2 * 64 * 128) + 128;   // 65664

// ---------------- CSR build ----------------
__global__ void count_edges(const int* __restrict__ src, const int* __restrict__ dst, int e) {
    int i = blockIdx.x * blockDim.x + threadIdx.x;
    if (i < e) {
        atomicAdd(&g_cnt_mi[src[i]], 1);
        atomicAdd(&g_cnt_di[dst[i]], 1);
    }
}

__global__ void scan2() {
    const int* cnt = blockIdx.x ? g_cnt_mi : g_cnt_di;
    int* rowptr    = blockIdx.x ? g_rowptr_mi : g_rowptr_di;
    int n          = blockIdx.x ? N_MI : N_DI;

    __shared__ int warpsum[32];
    __shared__ int s_running;
    int tid = threadIdx.x, lane = tid & 31, wid = tid >> 5;
    if (tid == 0) s_running = 0;
    __syncthreads();

    for (int base = 0; base < n; base += 1024) {
        int i = base + tid;
        int v = (i < n) ? cnt[i] : 0;
        int x = v;
        #pragma unroll
        for (int off = 1; off < 32; off <<= 1) {
            int t = __shfl_up_sync(0xffffffffu, x, off);
            if (lane >= off) x += t;
        }
        if (lane == 31) warpsum[wid] = x;
        __syncthreads();
        if (wid == 0) {
            int w = warpsum[lane];
            #pragma unroll
            for (int off = 1; off < 32; off <<= 1) {
                int t = __shfl_up_sync(0xffffffffu, w, off);
                if (lane >= off) w += t;
            }
            warpsum[lane] = w;
        }
        __syncthreads();
        int incl = x + (wid ? warpsum[wid - 1] : 0);
        int run = s_running;
        if (i < n) rowptr[i] = run + incl - v;
        __syncthreads();
        if (tid == 1023) s_running = run + warpsum[31];
        __syncthreads();
    }
    if (threadIdx.x == 0) rowptr[n] = s_running;
}

__global__ void fill_edges(const int* __restrict__ src, const int* __restrict__ dst, int e) {
    int i = blockIdx.x * blockDim.x + threadIdx.x;
    if (i < e) {
        int s = src[i], d = dst[i];
        int pd = g_rowptr_di[d] + atomicAdd(&g_cnt_di[d], 1);
        g_col_di[pd] = s;
        int pm = g_rowptr_mi[s] + atomicAdd(&g_cnt_mi[s], 1);
        g_col_mi[pm] = d;
    }
}

// ---------------- aggregation kernels ----------------
__global__ void agg_plain128(const float* __restrict__ x, const int* __restrict__ rowptr,
                             const int* __restrict__ col, float* __restrict__ out, int n) {
    int warp = (blockIdx.x * blockDim.x + threadIdx.x) >> 5;
    int lane = threadIdx.x & 31;
    if (warp >= n) return;
    int s = rowptr[warp], e = rowptr[warp + 1];
    float4 acc = make_float4(0.f, 0.f, 0.f, 0.f);
    int i = s;
    for (; i + 1 < e; i += 2) {
        float4 a = __ldg((const float4*)(x + (size_t)col[i] * 128) + lane);
        float4 b = __ldg((const float4*)(x + (size_t)col[i + 1] * 128) + lane);
        acc.x += a.x + b.x; acc.y += a.y + b.y;
        acc.z += a.z + b.z; acc.w += a.w + b.w;
    }
    if (i < e) {
        float4 a = __ldg((const float4*)(x + (size_t)col[i] * 128) + lane);
        acc.x += a.x; acc.y += a.y; acc.z += a.z; acc.w += a.w;
    }
    float inv = 1.f / fmaxf((float)(e - s), 1.f);
    acc.x *= inv; acc.y *= inv; acc.z *= inv; acc.w *= inv;
    ((float4*)(out + (size_t)warp * 128))[lane] = acc;
}

// L2: out = relu(mean(srcC[:,0:128]) + rootC[:,128:256]); stride 256
__global__ void agg_fused128(const float* __restrict__ srcC, const float* __restrict__ rootC,
                             const int* __restrict__ rowptr, const int* __restrict__ col,
                             float* __restrict__ out, int n) {
    int warp = (blockIdx.x * blockDim.x + threadIdx.x) >> 5;
    int lane = threadIdx.x & 31;
    if (warp >= n) return;
    int s = rowptr[warp], e = rowptr[warp + 1];
    float4 acc = make_float4(0.f, 0.f, 0.f, 0.f);
    int i = s;
    for (; i + 1 < e; i += 2) {
        float4 a = __ldg((const float4*)(srcC + (size_t)col[i] * 256) + lane);
        float4 b = __ldg((const float4*)(srcC + (size_t)col[i + 1] * 256) + lane);
        acc.x += a.x + b.x; acc.y += a.y + b.y;
        acc.z += a.z + b.z; acc.w += a.w + b.w;
    }
    if (i < e) {
        float4 a = __ldg((const float4*)(srcC + (size_t)col[i] * 256) + lane);
        acc.x += a.x; acc.y += a.y; acc.z += a.z; acc.w += a.w;
    }
    float inv = 1.f / fmaxf((float)(e - s), 1.f);
    float4 r = __ldg((const float4*)(rootC + (size_t)warp * 256 + 128) + lane);
    float4 v;
    v.x = fmaxf(acc.x * inv + r.x, 0.f);
    v.y = fmaxf(acc.y * inv + r.y, 0.f);
    v.z = fmaxf(acc.z * inv + r.z, 0.f);
    v.w = fmaxf(acc.w * inv + r.w, 0.f);
    ((float4*)(out + (size_t)warp * 128))[lane] = v;
}

// L3: out = mean(srcC[:,0:64]) + rootC[:,64:128]; stride 128, width 64
__global__ void agg_fused64(const float* __restrict__ srcC, const float* __restrict__ rootC,
                            const int* __restrict__ rowptr, const int* __restrict__ col,
                            float* __restrict__ out, int n) {
    int warp = (blockIdx.x * blockDim.x + threadIdx.x) >> 5;
    int lane = threadIdx.x & 31;
    if (warp >= n) return;
    int s = rowptr[warp], e = rowptr[warp + 1];
    float2 acc = make_float2(0.f, 0.f);
    int i = s;
    for (; i + 1 < e; i += 2) {
        float2 a = __ldg((const float2*)(srcC + (size_t)col[i] * 128) + lane);
        float2 b = __ldg((const float2*)(srcC + (size_t)col[i + 1] * 128) + lane);
        acc.x += a.x + b.x; acc.y += a.y + b.y;
    }
    if (i < e) {
        float2 a = __ldg((const float2*)(srcC + (size_t)col[i] * 128) + lane);
        acc.x += a.x; acc.y += a.y;
    }
    float inv = 1.f / fmaxf((float)(e - s), 1.f);
    float2 r = __ldg((const float2*)(rootC + (size_t)warp * 128 + 64) + lane);
    float2 v = make_float2(acc.x * inv + r.x, acc.y * inv + r.y);
    ((float2*)(out + (size_t)warp * 64))[lane] = v;
}

// ---------------- classifier ----------------
__global__ void dot64(const float* __restrict__ hmi, const float* __restrict__ hdi,
                      const int* __restrict__ lsrc, const int* __restrict__ ldst,
                      float* __restrict__ out, int L) {
    int warp = (blockIdx.x * blockDim.x + threadIdx.x) >> 5;
    int lane = threadIdx.x & 31;
    if (warp >= L) return;
    const float2* a = (const float2*)(hmi + (size_t)lsrc[warp] * 64);
    const float2* b = (const float2*)(hdi + (size_t)ldst[warp] * 64);
    float2 av = a[lane], bv = b[lane];
    float p = av.x * bv.x + av.y * bv.y;
    #pragma unroll
    for (int off = 16; off; off >>= 1) p += __shfl_down_sync(0xffffffffu, p, off);
    if (lane == 0) out[warp] = p;
}

// ---------------- host orchestration ----------------
static inline void gemm128(const float* A0, const float* A1,
                           const float* B0, const float* B1, int nsplit,
                           const float* bias, const float* addend,
                           float* C, int M, int N, int K, int relu) {
    mma_gemm<128><<<dim3(N / 128, (M + 63) / 64), 256, SMEM128>>>(
        A0, A1, B0, B1, nsplit, bias, addend, C, M, N, K, relu);
}
static inline void gemm64(const float* A0, const float* A1,
                          const float* B0, const float* B1, int nsplit,
                          const float* bias, const float* addend,
                          float* C, int M, int N, int K, int relu) {
    mma_gemm<64><<<dim3(N / 64, (M + 63) / 64), 256, SMEM64>>>(
        A0, A1, B0, B1, nsplit, bias, addend, C, M, N, K, relu);
}

extern "C" void kernel_launch(void* const* d_in, const int* in_sizes, int n_in,
                              void* d_out, int out_size) {
    const float* x_mi   = (const float*)d_in[0];
    const float* x_di   = (const float*)d_in[1];
    const float* W_mi   = (const float*)d_in[2];
    const float* b_mi   = (const float*)d_in[3];
    const float* W_di   = (const float*)d_in[4];
    const float* b_di   = (const float*)d_in[5];
    const float* emb_mi = (const float*)d_in[6];
    const float* emb_di = (const float*)d_in[7];
    const float *Wl[3][2], *bl[3][2], *Wr[3][2];   // [layer][0=md,1=dm]
    for (int i = 0; i < 3; ++i)
        for (int r = 0; r < 2; ++r) {
            int base = 8 + i * 6 + r * 3;
            Wl[i][r] = (const float*)d_in[base];
            bl[i][r] = (const float*)d_in[base + 1];
            Wr[i][r] = (const float*)d_in[base + 2];
        }
    const int* edge_src  = (const int*)d_in[26];
    const int* edge_dst  = (const int*)d_in[27];
    const int* label_src = (const int*)d_in[28];
    const int* label_dst = (const int*)d_in[29];
    float* out = (float*)d_out;

    cudaFuncSetAttribute(mma_gemm<128>, cudaFuncAttributeMaxDynamicSharedMemorySize, SMEM128);
    cudaFuncSetAttribute(mma_gemm<64>,  cudaFuncAttributeMaxDynamicSharedMemorySize, SMEM64);

    float *hA_mi, *hB_mi, *hA_di, *hB_di, *t_mi, *t_di;
    int *rp_di, *rp_mi, *col_di, *col_mi, *cnt_di, *cnt_mi;
    cudaGetSymbolAddress((void**)&hA_mi, g_hA_mi);
    cudaGetSymbolAddress((void**)&hB_mi, g_hB_mi);
    cudaGetSymbolAddress((void**)&hA_di, g_hA_di);
    cudaGetSymbolAddress((void**)&hB_di, g_hB_di);
    cudaGetSymbolAddress((void**)&t_mi, g_t_mi);
    cudaGetSymbolAddress((void**)&t_di, g_t_di);
    cudaGetSymbolAddress((void**)&rp_di, g_rowptr_di);
    cudaGetSymbolAddress((void**)&rp_mi, g_rowptr_mi);
    cudaGetSymbolAddress((void**)&col_di, g_col_di);
    cudaGetSymbolAddress((void**)&col_mi, g_col_mi);
    cudaGetSymbolAddress((void**)&cnt_di, g_cnt_di);
    cudaGetSymbolAddress((void**)&cnt_mi, g_cnt_mi);

    const int EB = (N_E + 255) / 256;
    const int AG_DI = (N_DI + 7) / 8;
    const int AG_MI = (N_MI + 7) / 8;

    // ---- CSR build ----
    cudaMemsetAsync(cnt_di, 0, N_DI * sizeof(int));
    cudaMemsetAsync(cnt_mi, 0, N_MI * sizeof(int));
    count_edges<<<EB, 256>>>(edge_src, edge_dst, N_E);
    scan2<<<2, 1024>>>();
    cudaMemsetAsync(cnt_di, 0, N_DI * sizeof(int));
    cudaMemsetAsync(cnt_mi, 0, N_MI * sizeof(int));
    fill_edges<<<EB, 256>>>(edge_src, edge_dst, N_E);

    // ---- input projections: h = x @ W^T + b + emb ----
    gemm128(x_mi, nullptr, W_mi, nullptr, 0, b_mi, emb_mi, hA_mi, N_MI, 128, F_MI_C, 0);
    gemm128(x_di, nullptr, W_di, nullptr, 0, b_di, emb_di, hA_di, N_DI, 128, F_DI_C, 0);

    // ---- Layer 1 (agg-first, 128 -> 256, relu), k-dual ----
    agg_plain128<<<AG_DI, 256>>>(hA_mi, rp_di, col_di, t_di, N_DI);
    agg_plain128<<<AG_MI, 256>>>(hA_di, rp_mi, col_mi, t_mi, N_MI);
    gemm128(t_di, hA_di, Wl[0][0], Wr[0][0], 0, bl[0][0], nullptr, hB_di, N_DI, 256, 128, 1);
    gemm128(t_mi, hA_mi, Wl[0][1], Wr[0][1], 0, bl[0][1], nullptr, hB_mi, N_MI, 256, 128, 1);

    // ---- Layer 2 (fused transform+root, 256 -> 128, relu) ----
    gemm128(hB_mi, nullptr, Wl[1][0], Wr[1][1], 128, bl[1][1], nullptr, t_mi, N_MI, 256, 256, 0);
    gemm128(hB_di, nullptr, Wl[1][1], Wr[1][0], 128, bl[1][0], nullptr, t_di, N_DI, 256, 256, 0);
    agg_fused128<<<AG_DI, 256>>>(t_mi, t_di, rp_di, col_di, hA_di, N_DI);
    agg_fused128<<<AG_MI, 256>>>(t_di, t_mi, rp_mi, col_mi, hA_mi, N_MI);

    // ---- Layer 3 (fused transform+root, 128 -> 64, no relu) ----
    gemm64(hA_mi, nullptr, Wl[2][0], Wr[2][1], 64, bl[2][1], nullptr, t_mi, N_MI, 128, 128, 0);
    gemm64(hA_di, nullptr, Wl[2][1], Wr[2][0], 64, bl[2][0], nullptr, t_di, N_DI, 128, 128, 0);
    agg_fused64<<<AG_DI, 256>>>(t_mi, t_di, rp_di, col_di, hB_di, N_DI);
    agg_fused64<<<AG_MI, 256>>>(t_di, t_mi, rp_mi, col_mi, hB_mi, N_MI);

    // ---- classifier ----
    dot64<<<(N_L + 7) / 8, 256>>>(hB_mi, hB_di, label_src, label_dst, out, N_L);
}